// round 12
// baseline (speedup 1.0000x reference)
#include <cuda_runtime.h>
#include <cuda_bf16.h>
#include <cuda_fp16.h>
#include <cstdint>

// Problem dims (fixed by the reference)
#define VOCAB 50000
#define EDIM  64
#define HDIM  64
#define BATCH 1024
#define SEQ   512

// Scratch: projected table proj[v][h] = b_ih[h]+b_hh[h] + sum_e emb[v,e]*W_ih[h,e]
__device__ float g_proj[VOCAB * HDIM];   // 12.8 MB, L2-resident in steady state
__device__ int   g_x64flag;              // 1 if token buffer is int64, 0 if int32

// Fast tanh: tanh(x) = 1 - 2/(1 + exp(2x)). ex2.approx + rcp.approx,
// rel err ~1e-6 (vs ~6e-4 for tanh.approx.f32).
__device__ __forceinline__ float fast_tanh(float x) {
    float e, r;
    asm("ex2.approx.f32 %0, %1;" : "=f"(e) : "f"(x * 2.885390081777927f)); // 2/ln2
    asm("rcp.approx.f32 %0, %1;" : "=f"(r) : "f"(e + 1.0f));
    return fmaf(-2.0f, r, 1.0f);
}

#define FMA2(acc, a, b) asm("fma.rn.f32x2 %0, %1, %2, %0;" : "+l"(acc) : "l"(a), "l"(b))
#define ADD2(acc, b)    asm("add.rn.f32x2 %0, %0, %1;"     : "+l"(acc) : "l"(b))
#define PACK2(d, lo, hi) asm("mov.b64 %0, {%1, %2};" : "=l"(d) : "f"(lo), "f"(hi))
#define UNPACK2(lo, hi, s) asm("mov.b64 {%0, %1}, %2;" : "=f"(lo), "=f"(hi) : "l"(s))

// ---------------------------------------------------------------------------
// Kernel A: build projected embedding table (fuses gather-side GEMM + biases).
// Block 0 warp 0 additionally detects int32-vs-int64 token layout: tokens are
// in [0,50000), so for little-endian int64 every odd 32-bit word is 0.
// ---------------------------------------------------------------------------
#define PROJ_ROWS 32
__global__ __launch_bounds__(256) void proj_kernel(
    const int*   __restrict__ x32,
    const float* __restrict__ emb,
    const float* __restrict__ W_ih,
    const float* __restrict__ b_ih,
    const float* __restrict__ b_hh)
{
    __shared__ float s_w[HDIM * 65];
    __shared__ float s_e[PROJ_ROWS * EDIM];
    __shared__ float s_bias[HDIM];

    const int t  = threadIdx.x;
    const int v0 = blockIdx.x * PROJ_ROWS;

    if (blockIdx.x == 0 && t < 32) {
        unsigned m = __ballot_sync(0xffffffff, x32[2 * t + 1] != 0);
        if (t == 0) g_x64flag = (m == 0u) ? 1 : 0;
    }

    #pragma unroll
    for (int k = 0; k < 16; k++) {
        int idx = t + k * 256;                 // 0..4095
        int hg = idx >> 6, eg = idx & 63;
        s_w[hg * 65 + eg] = W_ih[idx];
    }
    #pragma unroll
    for (int k = 0; k < 8; k++) {
        int idx = t + k * 256;                 // 0..2047
        int r = idx >> 6, e = idx & 63;
        s_e[idx] = (v0 + r < VOCAB) ? emb[(long)(v0 + r) * EDIM + e] : 0.0f;
    }
    if (t < HDIM) s_bias[t] = b_ih[t] + b_hh[t];
    __syncthreads();

    const int h    = t & 63;
    const int rgrp = t >> 6;                   // 0..3
    #pragma unroll
    for (int k = 0; k < 8; k++) {
        int r = rgrp + 4 * k;                  // 0..31
        if (v0 + r >= VOCAB) break;
        float acc = s_bias[h];
        #pragma unroll
        for (int e = 0; e < EDIM; e++)
            acc += s_e[r * EDIM + e] * s_w[h * 65 + e];
        g_proj[(v0 + r) * HDIM + h] = acc;
    }
}

// ---------------------------------------------------------------------------
// Kernel B: warp-private broadcast recurrence with fp16 h-TRANSPORT.
// Block = 128 threads = 4 warps (one per SMSP). Each warp = one batch row,
// fully autonomous (no __syncthreads in hot loop). Lane t owns outputs
// h[2t], h[2t+1] in fp32; weights/accum/tanh/xp all fp32. Only the inter-lane
// h exchange is quantized: lane stores its pair as one half2 (STS.32), reads
// the row's 64 h as 8 LDS.128 (128 B vs 256 B fp32 -> halves the MIO wall,
// which R11 showed is the chip-wide floor at ~443 cyc/step fp32).
// Precision: transport-only quantization, contractive recurrence -> ~1e-4
// output rel err (10x under the 1e-3 gate); fc uses fp32 register h.
// ---------------------------------------------------------------------------
__global__ __launch_bounds__(128, 2) void rnn_h16_kernel(
    const int*   __restrict__ x32,
    const float* __restrict__ W_hh,
    const float* __restrict__ fc_w,
    const float* __restrict__ fc_b,
    float*       __restrict__ out)
{
    __shared__ int      s_tok[4][SEQ];         // 8 KB  [warp][t]
    __shared__ uint32_t s_h[4][2][32];         // 1 KB  [warp][buf][lane] half2

    const int w    = threadIdx.x >> 5;         // warp in block: 0..3
    const int lane = threadIdx.x & 31;
    const int row  = blockIdx.x * 4 + w;
    const int flag = g_x64flag;

    // Tokens for this warp's row (handles int32 or int64 source layout)
    for (int k = lane; k < SEQ; k += 32) {
        long base = (long)row * SEQ + k;
        s_tok[w][k] = flag ? x32[2 * base] : x32[base];
    }
    __syncwarp();

    // Weights for outputs i0 = 2*lane, i1 = 2*lane+1, packed over j-pairs:
    // wp0[j] = (W[i0][2j], W[i0][2j+1]), wp1 likewise. 128 regs, no dup.
    unsigned long long wp0[32], wp1[32];
    {
        const ulonglong2* a = (const ulonglong2*)(W_hh + (2 * lane)     * HDIM);
        const ulonglong2* b = (const ulonglong2*)(W_hh + (2 * lane + 1) * HDIM);
        #pragma unroll
        for (int q = 0; q < 16; q++) {
            ulonglong2 u = a[q]; wp0[2 * q] = u.x; wp0[2 * q + 1] = u.y;
            ulonglong2 v = b[q]; wp1[2 * q] = v.x; wp1[2 * q + 1] = v.y;
        }
    }

    // h init (buffer 0): half2(0,0)
    s_h[w][0][lane] = 0u;
    __syncwarp();

    float h0 = 0.0f, h1 = 0.0f;

    // xp register pipeline, depth 3 (covers ~3 steps of L2 latency)
    float2 xp0 = *(const float2*)(g_proj + s_tok[w][0] * HDIM + 2 * lane);
    float2 xp1 = *(const float2*)(g_proj + s_tok[w][1] * HDIM + 2 * lane);
    float2 xp2 = *(const float2*)(g_proj + s_tok[w][2] * HDIM + 2 * lane);

    #pragma unroll 2
    for (int t = 0; t < SEQ; t++) {
        const int cur = t & 1, nxt = cur ^ 1;
        const int tp = (t + 3 < SEQ) ? (t + 3) : (SEQ - 1);
        float2 xpf = *(const float2*)(g_proj + s_tok[w][tp] * HDIM + 2 * lane);

        // 8 accumulators: chain depth 8 (-> ~32 cyc serial in the FMA stage)
        unsigned long long a00, a01 = 0ULL, a02 = 0ULL, a03 = 0ULL;
        unsigned long long a10, a11 = 0ULL, a12 = 0ULL, a13 = 0ULL;
        PACK2(a00, xp0.x, 0.0f);
        PACK2(a10, xp0.y, 0.0f);

        // 8 LDS.128 over the warp's half2 h line (128 B total)
        const uint4* hp = (const uint4*)s_h[w][cur];
        #pragma unroll
        for (int q = 0; q < 8; q++) {          // uint4 = j-pairs 4q..4q+3
            uint4 u = hp[q];
            float2 f0 = __half22float2(*(const __half2*)&u.x);
            float2 f1 = __half22float2(*(const __half2*)&u.y);
            float2 f2 = __half22float2(*(const __half2*)&u.z);
            float2 f3 = __half22float2(*(const __half2*)&u.w);
            unsigned long long p0, p1, p2, p3;
            PACK2(p0, f0.x, f0.y);
            PACK2(p1, f1.x, f1.y);
            PACK2(p2, f2.x, f2.y);
            PACK2(p3, f3.x, f3.y);
            FMA2(a00, p0, wp0[4 * q + 0]);
            FMA2(a01, p1, wp0[4 * q + 1]);
            FMA2(a02, p2, wp0[4 * q + 2]);
            FMA2(a03, p3, wp0[4 * q + 3]);
            FMA2(a10, p0, wp1[4 * q + 0]);
            FMA2(a11, p1, wp1[4 * q + 1]);
            FMA2(a12, p2, wp1[4 * q + 2]);
            FMA2(a13, p3, wp1[4 * q + 3]);
        }
        ADD2(a00, a01); ADD2(a02, a03); ADD2(a00, a02);
        ADD2(a10, a11); ADD2(a12, a13); ADD2(a10, a12);

        float e0, o0, e1, o1;
        UNPACK2(e0, o0, a00);
        UNPACK2(e1, o1, a10);
        h0 = fast_tanh(e0 + o0);
        h1 = fast_tanh(e1 + o1);

        // Publish own pair as half2 (one cvt.rn.f16x2.f32 + STS.32)
        __half2 hq = __floats2half2_rn(h0, h1);
        s_h[w][nxt][lane] = *(const uint32_t*)&hq;
        __syncwarp();

        xp0 = xp1;
        xp1 = xp2;
        xp2 = xpf;
    }

    // fc + sigmoid: logit = sum_i h[i]*fc_w[i] + fc_b[0]  (fp32 register h)
    float2 f = *(const float2*)(fc_w + 2 * lane);
    float v = h0 * f.x + h1 * f.y;
    #pragma unroll
    for (int off = 16; off; off >>= 1)
        v += __shfl_xor_sync(0xffffffffu, v, off);
    if (lane == 0)
        out[row] = 1.0f / (1.0f + expf(-(v + fc_b[0])));
}

// ---------------------------------------------------------------------------
// Launch. Inputs (metadata order): x, emb, W_ih, W_hh, b_ih, b_hh, fc_w, fc_b
// 2 launches/call so ncu -s 5 -c 1 lands on rnn_h16_kernel.
// ---------------------------------------------------------------------------
extern "C" void kernel_launch(void* const* d_in, const int* in_sizes, int n_in,
                              void* d_out, int out_size)
{
    const int*   x32  = (const int*)  d_in[0];
    const float* emb  = (const float*)d_in[1];
    const float* W_ih = (const float*)d_in[2];
    const float* W_hh = (const float*)d_in[3];
    const float* b_ih = (const float*)d_in[4];
    const float* b_hh = (const float*)d_in[5];
    const float* fc_w = (const float*)d_in[6];
    const float* fc_b = (const float*)d_in[7];
    float* out = (float*)d_out;

    proj_kernel<<<(VOCAB + PROJ_ROWS - 1) / PROJ_ROWS, 256>>>(x32, emb, W_ih, b_ih, b_hh);
    rnn_h16_kernel<<<BATCH / 4, 128>>>(x32, W_hh, fc_w, fc_b, out);
}